// round 14
// baseline (speedup 1.0000x reference)
#include <cuda_runtime.h>
#include <math.h>

#define N_NODES   24000
#define NT_NODES  8000
#define NUM_T     3
#define NUM_R     34
#define EPR       10000
#define NH        8
#define DKQ       16
#define D         128
#define EBLK2     157            // ceil(10000/64) blocks (64 edges/block, 2 per thread)

// Swizzled node-feature layout for k/q/v/t:
//   element (h, f) of a node lives at  chunk j = f/4, offset  j*32 + h*4 + (f%4)
// so one head's j-th float4 for the 8 heads of a warp-group is 128B contiguous.

// ---------------- scratch (device globals; no allocation allowed) ----------
__device__ float g_k[N_NODES * D];
__device__ float g_q[N_NODES * D];
__device__ float g_v[N_NODES * D];
__device__ float g_e[NUM_R * EPR * NH];          // exp(score) per edge/head
__device__ float g_den[NUM_R * NT_NODES * NH];   // softmax denom -> inverted in-place
__device__ unsigned long long g_mask[N_NODES];   // relation bitmask per dst node
__device__ float g_t[N_NODES * D];               // aggregated messages (swizzled)

// relation -> node-type maps (compile-time formulas from reference)
__device__ __forceinline__ int src_nt(int r) { return r <= 9 ? 0 : (r <= 21 ? 1 : 2); }
__device__ __forceinline__ int dst_nt(int r) {
    if (r <= 2 || (r >= 10 && r <= 13) || (r >= 22 && r <= 24)) return 0;
    if ((r >= 3 && r <= 6) || (r >= 14 && r <= 17) || (r >= 25 && r <= 28)) return 1;
    return 2;
}

// ---------------- packed f32x2 helpers (Blackwell FFMA2) --------------------
__device__ __forceinline__ double splat2(float x) {
    double r; asm("mov.b64 %0, {%1, %1};" : "=d"(r) : "f"(x)); return r;
}
__device__ __forceinline__ void fma2(double& d, double a, double b) {
    asm("fma.rn.f32x2 %0, %1, %2, %0;" : "+d"(d) : "d"(a), "d"(b));
}
__device__ __forceinline__ void mul2(double& d, double a) {
    asm("mul.rn.f32x2 %0, %0, %1;" : "+d"(d) : "d"(a));
}
__device__ __forceinline__ float2 unpack2(double d) {
    float lo, hi; asm("mov.b64 {%0, %1}, %2;" : "=f"(lo), "=f"(hi) : "d"(d));
    return make_float2(lo, hi);
}
__device__ __forceinline__ float fcomp(float4 a, float4 b, int i) {
    switch (i) {
        case 0: return a.x; case 1: return a.y; case 2: return a.z; case 3: return a.w;
        case 4: return b.x; case 5: return b.y; case 6: return b.z; default: return b.w;
    }
}
__device__ __forceinline__ float fcomp4(float4 a, int i) {
    switch (i) {
        case 0: return a.x; case 1: return a.y; case 2: return a.z; default: return a.w;
    }
}

// ---------------- typed K/Q/V projections (3 dense GEMMs per type) ----------
// Flattened (p,kc) loop with register prefetch of the next W chunk. The 16-kk
// inner loop runs in 4 passes of 4 kk with wreg[4] (same LDS count, -48 regs
// vs wreg[16]) so the kernel fits 3 CTAs/SM. Prologue zeroes g_den/g_t/g_mask
// while the x LDGs are in flight. Output swizzled: col -> (col%16)/4*32+(col/16)*4.
__global__ __launch_bounds__(256, 3) void proj3_kernel(
    const float* __restrict__ x,
    const float* __restrict__ Wk, const float* __restrict__ bk,
    const float* __restrict__ Wq, const float* __restrict__ bq,
    const float* __restrict__ Wv, const float* __restrict__ bv)
{
    __shared__ float xs[64 * D];
    __shared__ float ws[16 * D];
    int node0 = blockIdx.x * 64;
    int t = node0 / NT_NODES;
    int tid = threadIdx.x;

    // issue x loads first
    float4 xtmp[8];
    {
        const float4* xg = (const float4*)(x + (size_t)node0 * D);
        #pragma unroll
        for (int i = 0; i < 8; i++) xtmp[i] = xg[tid + i * 256];
    }

    // zero scratch (grid-stride) while x loads are in flight
    {
        int gtid = blockIdx.x * 256 + tid;
        int gstride = (N_NODES / 64) * 256;
        float4 z = make_float4(0.f, 0.f, 0.f, 0.f);
        float4* den4 = (float4*)g_den;
        for (int i = gtid; i < (NUM_R * NT_NODES * NH) / 4; i += gstride) den4[i] = z;
        float4* t4 = (float4*)g_t;
        for (int i = gtid; i < (N_NODES * D) / 4; i += gstride) t4[i] = z;
        for (int i = gtid; i < N_NODES; i += gstride) g_mask[i] = 0ull;
    }

    const float* Wp[3] = { Wk + t * D * D, Wq + t * D * D, Wv + t * D * D };
    const float* bp[3] = { bk + t * D,     bq + t * D,     bv + t * D };
    float* op[3] = { g_k, g_q, g_v };

    // prefetch W chunk 0
    float4 wt0, wt1;
    {
        const float4* wg = (const float4*)Wp[0];
        wt0 = wg[tid]; wt1 = wg[tid + 256];
    }
    {
        float4* xs4 = (float4*)xs;
        #pragma unroll
        for (int i = 0; i < 8; i++) xs4[tid + i * 256] = xtmp[i];
    }

    int col = (tid & 31) * 4;
    int row = (tid >> 5) * 8;
    int newcol = ((col >> 2) & 3) * 32 + (col >> 4) * 4;   // swizzled target
    double acc[8][2];
    #pragma unroll
    for (int i = 0; i < 8; i++) { acc[i][0] = 0.0; acc[i][1] = 0.0; }

    for (int it = 0; it < 24; it++) {
        __syncthreads();
        float4* ws4 = (float4*)ws;
        ws4[tid] = wt0;
        ws4[tid + 256] = wt1;
        __syncthreads();
        if (it < 23) {                       // prefetch next chunk (overlaps compute)
            int p2 = (it + 1) >> 3, kc2 = (it + 1) & 7;
            const float4* wg = (const float4*)(Wp[p2] + kc2 * 16 * D);
            wt0 = wg[tid]; wt1 = wg[tid + 256];
        }
        int kc = it & 7;
        #pragma unroll
        for (int kq = 0; kq < 4; kq++) {     // 4 passes of 4 kk: wreg stays at 4
            double2 wreg[4];
            #pragma unroll
            for (int kk = 0; kk < 4; kk++)
                wreg[kk] = *(const double2*)&ws[(kq * 4 + kk) * D + col];
            #pragma unroll
            for (int i = 0; i < 8; i++) {
                float4 xa = *(const float4*)&xs[(row + i) * D + kc * 16 + kq * 4];
                #pragma unroll
                for (int kk = 0; kk < 4; kk++) {
                    double xv2 = splat2(fcomp4(xa, kk));
                    fma2(acc[i][0], xv2, wreg[kk].x);
                    fma2(acc[i][1], xv2, wreg[kk].y);
                }
            }
        }
        if (kc == 7) {
            int p = it >> 3;
            float4 bb = *(const float4*)&bp[p][col];
            float* o = op[p];
            #pragma unroll
            for (int i = 0; i < 8; i++) {
                float2 p0 = unpack2(acc[i][0]);
                float2 p1 = unpack2(acc[i][1]);
                float4 rr = make_float4(p0.x + bb.x, p0.y + bb.y, p1.x + bb.z, p1.y + bb.w);
                *(float4*)&o[(size_t)(node0 + row + i) * D + newcol] = rr;
                acc[i][0] = 0.0; acc[i][1] = 0.0;
            }
        }
    }
}

// ---------------- edge scores -----------------------------------------------
// 2 edges/thread, kt-form, swizzled gathers. na dots computed inline.
__global__ __launch_bounds__(256, 4) void edge_score_kernel(
    const int* __restrict__ src, const int* __restrict__ dst,
    const float* __restrict__ rel_att, const float* __restrict__ rel_pri,
    const float* __restrict__ nta, const float* __restrict__ nta1,
    const float* __restrict__ weight, const float* __restrict__ attn_w)
{
    __shared__ float4 ratt4[16 * 4 * NH];   // [dd][f4][h]
    __shared__ float pri[NH];
    __shared__ float4 wq4[4];               // wq, chunk-packed (16 floats)
    __shared__ float wks[16];               // wk scalars
    int r = blockIdx.y;
    int tid = threadIdx.x;
    {
        float* ratt = (float*)ratt4;
        #pragma unroll
        for (int it = 0; it < 8; it++) {
            int i = tid + it * 256;                       // = h*256 + dd*16 + f
            int hh = i >> 8, dd = (i >> 4) & 15, ff = i & 15;
            ratt[((dd * 4 + (ff >> 2)) * NH + hh) * 4 + (ff & 3)] = rel_att[r * 2048 + i];
        }
    }
    if (tid < NH) pri[tid] = rel_pri[r * NH + tid] * 0.25f;  // fold 1/sqrt(16)
    if (tid >= 32 && tid < 48) ((float*)wq4)[tid - 32] = attn_w[tid - 32];
    if (tid >= 48 && tid < 64) wks[tid - 48] = attn_w[tid - 32];
    __syncthreads();

    int h = tid & 7;
    int e0 = blockIdx.x * 64 + (tid >> 3) * 2;
    if (e0 >= EPR) return;
    bool has1 = (e0 + 1) < EPR;
    int e1 = has1 ? e0 + 1 : e0;

    int s0 = src[r * EPR + e0], d0 = dst[r * EPR + e0];
    int s1 = src[r * EPR + e1], d1 = dst[r * EPR + e1];

    const double2* A2 = (const double2*)ratt4;
    double kt0[8], kt1[8];
    #pragma unroll
    for (int p = 0; p < 8; p++) { kt0[p] = 0.0; kt1[p] = 0.0; }
    float kw0 = 0.f, kw1 = 0.f;

    const float4* kb0 = (const float4*)(g_k + (size_t)s0 * D);
    const float4* kb1 = (const float4*)(g_k + (size_t)s1 * D);
    #pragma unroll
    for (int dh = 0; dh < 2; dh++) {
        float4 ka0 = kb0[(dh * 2) * 8 + h], kc0 = kb0[(dh * 2 + 1) * 8 + h];
        float4 ka1 = kb1[(dh * 2) * 8 + h], kc1 = kb1[(dh * 2 + 1) * 8 + h];
        #pragma unroll
        for (int di = 0; di < 8; di++) {
            int dd = dh * 8 + di;
            float k0f = fcomp(ka0, kc0, di);
            float k1f = fcomp(ka1, kc1, di);
            float wkd = wks[dd];
            kw0 = fmaf(wkd, k0f, kw0);
            kw1 = fmaf(wkd, k1f, kw1);
            double k0s = splat2(k0f);
            double k1s = splat2(k1f);
            #pragma unroll
            for (int f4 = 0; f4 < 4; f4++) {
                double2 m = A2[(dd * 4 + f4) * NH + h];   // shared by both edges
                fma2(kt0[2 * f4],     k0s, m.x);
                fma2(kt0[2 * f4 + 1], k0s, m.y);
                fma2(kt1[2 * f4],     k1s, m.x);
                fma2(kt1[2 * f4 + 1], k1s, m.y);
            }
        }
    }

    // dot with q (loaded only now, after k registers die); also q.wq inline
    double s20 = 0.0, s21 = 0.0, qa0 = 0.0, qa1 = 0.0;
    {
        const double2* qb0 = (const double2*)(g_q + (size_t)d0 * D);
        const double2* qb1 = (const double2*)(g_q + (size_t)d1 * D);
        const double2* WQ = (const double2*)wq4;
        #pragma unroll
        for (int j = 0; j < 4; j++) {
            double2 wq = WQ[j];
            double2 q0 = qb0[j * 8 + h];                  // chunk j of head h
            fma2(s20, kt0[2 * j],     q0.x);
            fma2(s20, kt0[2 * j + 1], q0.y);
            fma2(qa0, wq.x, q0.x);
            fma2(qa0, wq.y, q0.y);
            double2 q1 = qb1[j * 8 + h];
            fma2(s21, kt1[2 * j],     q1.x);
            fma2(s21, kt1[2 * j + 1], q1.y);
            fma2(qa1, wq.x, q1.x);
            fma2(qa1, wq.y, q1.y);
        }
    }
    float prh = pri[h];
    float2 u0 = unpack2(s20);
    float a0 = (u0.x + u0.y) * prh;
    float2 u1 = unpack2(s21);
    float a1 = (u1.x + u1.y) * prh;
    float2 w0 = unpack2(qa0);
    float qw0 = w0.x + w0.y;
    float2 w1 = unpack2(qa1);
    float qw1 = w1.x + w1.y;

    int snt = src_nt(r), dnt = dst_nt(r);
    float ntaS = nta[snt], ntaD = nta1[dnt];
    float beta = 1.f / (1.f + __expf(-weight[0]));
    {
        float na = ntaD * qw0 + ntaS * kw0;
        na = na > 0.f ? na : 0.01f * na;
        float ev = __expf(a0 + beta * na);
        g_e[((size_t)r * EPR + e0) * NH + h] = ev;
        atomicAdd(&g_den[((size_t)r * NT_NODES + (d0 - dnt * NT_NODES)) * NH + h], ev);
        if (h == 0) atomicOr(&g_mask[d0], 1ull << r);
    }
    if (has1) {
        float na = ntaD * qw1 + ntaS * kw1;
        na = na > 0.f ? na : 0.01f * na;
        float ev = __expf(a1 + beta * na);
        g_e[((size_t)r * EPR + e1) * NH + h] = ev;
        atomicAdd(&g_den[((size_t)r * NT_NODES + (d1 - dnt * NT_NODES)) * NH + h], ev);
        if (h == 0) atomicOr(&g_mask[d1], 1ull << r);
    }
}

// ---------------- invert denominators, folding 1/nrel (x4 vectorized) -------
__global__ void deninv_kernel() {
    int i4 = blockIdx.x * blockDim.x + threadIdx.x;
    if (i4 >= (NUM_R * NT_NODES * NH) / 4) return;
    int idx = i4 * 4;
    int r = idx / (NT_NODES * NH);
    int rem = idx - r * (NT_NODES * NH);
    int dl = rem / NH;
    int d = dst_nt(r) * NT_NODES + dl;
    int c = __popcll(g_mask[d]);
    float cf = (float)(c > 0 ? c : 1);
    float4 den = *(float4*)&g_den[idx];
    den.x = den.x > 0.f ? __fdividef(1.f, den.x * cf) : 0.f;
    den.y = den.y > 0.f ? __fdividef(1.f, den.y * cf) : 0.f;
    den.z = den.z > 0.f ? __fdividef(1.f, den.z * cf) : 0.f;
    den.w = den.w > 0.f ? __fdividef(1.f, den.w * cf) : 0.f;
    *(float4*)&g_den[idx] = den;
}

// ---------------- message transform + weighted scatter into t ---------------
// 2 edges/thread; swizzled v gathers and t scatters. e/den loads hoisted
// before the transform loop so their latency overlaps the FMA work.
__global__ __launch_bounds__(256, 4) void edge_accum_kernel(
    const int* __restrict__ src, const int* __restrict__ dst,
    const float* __restrict__ rel_msg)
{
    __shared__ float4 rm4[16 * 4 * NH];   // [dd][f4][h]
    int r = blockIdx.y;
    int tid = threadIdx.x;
    {
        float* rm = (float*)rm4;
        #pragma unroll
        for (int it = 0; it < 8; it++) {
            int i = tid + it * 256;
            int hh = i >> 8, dd = (i >> 4) & 15, ff = i & 15;
            rm[((dd * 4 + (ff >> 2)) * NH + hh) * 4 + (ff & 3)] = rel_msg[r * 2048 + i];
        }
    }
    __syncthreads();

    int h = tid & 7;
    int e0 = blockIdx.x * 64 + (tid >> 3) * 2;
    if (e0 >= EPR) return;
    bool has1 = (e0 + 1) < EPR;
    int e1 = has1 ? e0 + 1 : e0;
    int dnt = dst_nt(r);

    int s0 = src[r * EPR + e0], d0 = dst[r * EPR + e0];
    int s1 = src[r * EPR + e1], d1 = dst[r * EPR + e1];

    // hoisted: softmax weight operands (consumed after the transform loop)
    float ew0 = g_e[((size_t)r * EPR + e0) * NH + h];
    float ew1 = g_e[((size_t)r * EPR + e1) * NH + h];
    float dn0 = g_den[((size_t)r * NT_NODES + (d0 - dnt * NT_NODES)) * NH + h];
    float dn1 = g_den[((size_t)r * NT_NODES + (d1 - dnt * NT_NODES)) * NH + h];

    const double2* M2 = (const double2*)rm4;
    double acc0[8], acc1[8];
    #pragma unroll
    for (int p = 0; p < 8; p++) { acc0[p] = 0.0; acc1[p] = 0.0; }

    const float4* vb0 = (const float4*)(g_v + (size_t)s0 * D);
    const float4* vb1 = (const float4*)(g_v + (size_t)s1 * D);
    #pragma unroll
    for (int dh = 0; dh < 2; dh++) {
        float4 va0 = vb0[(dh * 2) * 8 + h], vc0 = vb0[(dh * 2 + 1) * 8 + h];
        float4 va1 = vb1[(dh * 2) * 8 + h], vc1 = vb1[(dh * 2 + 1) * 8 + h];
        #pragma unroll
        for (int di = 0; di < 8; di++) {
            int dd = dh * 8 + di;
            double v0s = splat2(fcomp(va0, vc0, di));
            double v1s = splat2(fcomp(va1, vc1, di));
            #pragma unroll
            for (int f4 = 0; f4 < 4; f4++) {
                double2 m = M2[(dd * 4 + f4) * NH + h];   // shared by both edges
                fma2(acc0[2 * f4],     v0s, m.x);
                fma2(acc0[2 * f4 + 1], v0s, m.y);
                fma2(acc1[2 * f4],     v1s, m.x);
                fma2(acc1[2 * f4 + 1], v1s, m.y);
            }
        }
    }

    double w0s = splat2(ew0 * dn0), w1s = splat2(ew1 * dn1);
    #pragma unroll
    for (int p = 0; p < 8; p++) { mul2(acc0[p], w0s); mul2(acc1[p], w1s); }

    float* tp0 = g_t + (size_t)d0 * D + h * 4;
    #pragma unroll
    for (int f4 = 0; f4 < 4; f4++) {
        float2 o0 = unpack2(acc0[2 * f4]);
        float2 o1 = unpack2(acc0[2 * f4 + 1]);
        asm volatile("red.global.add.v4.f32 [%0], {%1, %2, %3, %4};"
                     :: "l"(tp0 + f4 * 32),
                        "f"(o0.x), "f"(o0.y), "f"(o1.x), "f"(o1.y)
                     : "memory");
    }
    if (has1) {
        float* tp1 = g_t + (size_t)d1 * D + h * 4;
        #pragma unroll
        for (int f4 = 0; f4 < 4; f4++) {
            float2 o0 = unpack2(acc1[2 * f4]);
            float2 o1 = unpack2(acc1[2 * f4 + 1]);
            asm volatile("red.global.add.v4.f32 [%0], {%1, %2, %3, %4};"
                         :: "l"(tp1 + f4 * 32),
                            "f"(o0.x), "f"(o0.y), "f"(o1.x), "f"(o1.y)
                         : "memory");
        }
    }
}

// ---------------- final typed projection + gated skip ------------------------
// g_t (swizzled) -> SMEM standard order; GEMM with W-chunk register prefetch
// and 4-kk wreg passes (low register pressure).
__global__ __launch_bounds__(256, 3) void final_kernel(
    const float* __restrict__ x,
    const float* __restrict__ Wa, const float* __restrict__ ba,
    const float* __restrict__ skip, float* __restrict__ out)
{
    __shared__ float xs[64 * D];
    __shared__ float ws[16 * D];
    int node0 = blockIdx.x * 64;
    int t = node0 / NT_NODES;
    int tid = threadIdx.x;

    float4 ttmp[8];
    {
        const float4* tg = (const float4*)(g_t + (size_t)node0 * D);
        #pragma unroll
        for (int i = 0; i < 8; i++) ttmp[i] = tg[tid + i * 256];
    }
    const float* Wp = Wa + t * D * D;
    float4 wt0, wt1;
    {
        const float4* wg = (const float4*)Wp;
        wt0 = wg[tid]; wt1 = wg[tid + 256];
    }
    {
        float4* xs4 = (float4*)xs;
        #pragma unroll
        for (int i = 0; i < 8; i++) {
            int idx = tid + i * 256;
            int nl = idx >> 5, c = idx & 31;           // swizzled chunk c = j*8+h
            int stdc = ((c & 7) << 2) + (c >> 3);      // std chunk = h*4+j
            xs4[nl * 32 + stdc] = ttmp[i];
        }
    }

    int col = (tid & 31) * 4;
    int row = (tid >> 5) * 8;
    double acc[8][2];
    #pragma unroll
    for (int i = 0; i < 8; i++) { acc[i][0] = 0.0; acc[i][1] = 0.0; }

    for (int kc = 0; kc < 8; kc++) {
        __syncthreads();
        float4* ws4 = (float4*)ws;
        ws4[tid] = wt0;
        ws4[tid + 256] = wt1;
        __syncthreads();
        if (kc < 7) {                        // prefetch next chunk
            const float4* wg = (const float4*)(Wp + (kc + 1) * 16 * D);
            wt0 = wg[tid]; wt1 = wg[tid + 256];
        }
        #pragma unroll
        for (int kq = 0; kq < 4; kq++) {     // 4 passes of 4 kk
            double2 wreg[4];
            #pragma unroll
            for (int kk = 0; kk < 4; kk++)
                wreg[kk] = *(const double2*)&ws[(kq * 4 + kk) * D + col];
            #pragma unroll
            for (int i = 0; i < 8; i++) {
                float4 xa = *(const float4*)&xs[(row + i) * D + kc * 16 + kq * 4];
                #pragma unroll
                for (int kk = 0; kk < 4; kk++) {
                    double xv2 = splat2(fcomp4(xa, kk));
                    fma2(acc[i][0], xv2, wreg[kk].x);
                    fma2(acc[i][1], xv2, wreg[kk].y);
                }
            }
        }
    }
    float alpha = 1.f / (1.f + __expf(-skip[t]));
    float onema = 1.f - alpha;
    float4 bb = *(const float4*)&ba[t * D + col];
    #pragma unroll
    for (int i = 0; i < 8; i++) {
        size_t off = (size_t)(node0 + row + i) * D + col;
        float4 xv = *(const float4*)&x[off];
        float2 p0 = unpack2(acc[i][0]);
        float2 p1 = unpack2(acc[i][1]);
        float4 rr;
        rr.x = (p0.x + bb.x) * alpha + xv.x * onema;
        rr.y = (p0.y + bb.y) * alpha + xv.y * onema;
        rr.z = (p1.x + bb.z) * alpha + xv.z * onema;
        rr.w = (p1.y + bb.w) * alpha + xv.w * onema;
        *(float4*)&out[off] = rr;
    }
}

// ---------------- launch ------------------------------------------------------
extern "C" void kernel_launch(void* const* d_in, const int* in_sizes, int n_in,
                              void* d_out, int out_size)
{
    const float* x       = (const float*)d_in[0];
    const int*   src     = (const int*)  d_in[1];
    const int*   dst     = (const int*)  d_in[2];
    const float* Wk      = (const float*)d_in[3];
    const float* bk      = (const float*)d_in[4];
    const float* Wq      = (const float*)d_in[5];
    const float* bq      = (const float*)d_in[6];
    const float* Wv      = (const float*)d_in[7];
    const float* bv      = (const float*)d_in[8];
    const float* Wa      = (const float*)d_in[9];
    const float* ba      = (const float*)d_in[10];
    const float* rel_att = (const float*)d_in[11];
    const float* rel_msg = (const float*)d_in[12];
    const float* rel_pri = (const float*)d_in[13];
    const float* nta     = (const float*)d_in[14];
    const float* nta1    = (const float*)d_in[15];
    const float* skip    = (const float*)d_in[16];
    const float* weight  = (const float*)d_in[17];
    const float* attn_w  = (const float*)d_in[18];
    float* out = (float*)d_out;

    proj3_kernel<<<N_NODES / 64, 256>>>(x, Wk, bk, Wq, bq, Wv, bv);
    edge_score_kernel<<<dim3(EBLK2, NUM_R), 256>>>(src, dst, rel_att, rel_pri, nta, nta1, weight, attn_w);
    deninv_kernel<<<((NUM_R * NT_NODES * NH) / 4 + 255) / 256, 256>>>();
    edge_accum_kernel<<<dim3(EBLK2, NUM_R), 256>>>(src, dst, rel_msg);
    final_kernel<<<N_NODES / 64, 256>>>(x, Wa, ba, skip, out);
}

// round 15
// speedup vs baseline: 1.0278x; 1.0278x over previous
#include <cuda_runtime.h>
#include <math.h>

#define N_NODES   24000
#define NT_NODES  8000
#define NUM_T     3
#define NUM_R     34
#define EPR       10000
#define NH        8
#define DKQ       16
#define D         128
#define EBLK2     157            // ceil(10000/64) blocks (64 edges/block, 2 per thread)

// Swizzled node-feature layout for k/q/v/t:
//   element (h, f) of a node lives at  chunk j = f/4, offset  j*32 + h*4 + (f%4)
// so one head's j-th float4 for the 8 heads of a warp-group is 128B contiguous.

// ---------------- scratch (device globals; no allocation allowed) ----------
__device__ float g_k[N_NODES * D];
__device__ float g_q[N_NODES * D];
__device__ float g_v[N_NODES * D];
__device__ float g_e[NUM_R * EPR * NH];          // exp(score) per edge/head
__device__ float g_den[NUM_R * NT_NODES * NH];   // softmax denom -> inverted in-place
__device__ unsigned long long g_mask[N_NODES];   // relation bitmask per dst node
__device__ float g_t[N_NODES * D];               // aggregated messages (swizzled)

// relation -> node-type maps (compile-time formulas from reference)
__device__ __forceinline__ int src_nt(int r) { return r <= 9 ? 0 : (r <= 21 ? 1 : 2); }
__device__ __forceinline__ int dst_nt(int r) {
    if (r <= 2 || (r >= 10 && r <= 13) || (r >= 22 && r <= 24)) return 0;
    if ((r >= 3 && r <= 6) || (r >= 14 && r <= 17) || (r >= 25 && r <= 28)) return 1;
    return 2;
}

// ---------------- packed f32x2 helpers (Blackwell FFMA2) --------------------
__device__ __forceinline__ double splat2(float x) {
    double r; asm("mov.b64 %0, {%1, %1};" : "=d"(r) : "f"(x)); return r;
}
__device__ __forceinline__ void fma2(double& d, double a, double b) {
    asm("fma.rn.f32x2 %0, %1, %2, %0;" : "+d"(d) : "d"(a), "d"(b));
}
__device__ __forceinline__ void mul2(double& d, double a) {
    asm("mul.rn.f32x2 %0, %0, %1;" : "+d"(d) : "d"(a));
}
__device__ __forceinline__ float2 unpack2(double d) {
    float lo, hi; asm("mov.b64 {%0, %1}, %2;" : "=f"(lo), "=f"(hi) : "d"(d));
    return make_float2(lo, hi);
}
__device__ __forceinline__ float fcomp(float4 a, float4 b, int i) {
    switch (i) {
        case 0: return a.x; case 1: return a.y; case 2: return a.z; case 3: return a.w;
        case 4: return b.x; case 5: return b.y; case 6: return b.z; default: return b.w;
    }
}
__device__ __forceinline__ float fcomp16(float4 a, float4 b, float4 c, float4 d, int i) {
    return i < 8 ? fcomp(a, b, i) : fcomp(c, d, i - 8);
}

// ---------------- typed K/Q/V projections (3 dense GEMMs per type) ----------
// Flattened (p,kc) loop with register prefetch of the next W chunk so the W
// LDG latency overlaps compute. Prologue zeroes g_den/g_t/g_mask while the x
// LDGs are in flight. Output stored swizzled: col -> (col%16)/4*32+(col/16)*4.
__global__ __launch_bounds__(256) void proj3_kernel(
    const float* __restrict__ x,
    const float* __restrict__ Wk, const float* __restrict__ bk,
    const float* __restrict__ Wq, const float* __restrict__ bq,
    const float* __restrict__ Wv, const float* __restrict__ bv)
{
    __shared__ float xs[64 * D];
    __shared__ float ws[16 * D];
    int node0 = blockIdx.x * 64;
    int t = node0 / NT_NODES;
    int tid = threadIdx.x;

    // issue x loads first
    float4 xtmp[8];
    {
        const float4* xg = (const float4*)(x + (size_t)node0 * D);
        #pragma unroll
        for (int i = 0; i < 8; i++) xtmp[i] = xg[tid + i * 256];
    }

    // zero scratch (grid-stride) while x loads are in flight
    {
        int gtid = blockIdx.x * 256 + tid;
        int gstride = (N_NODES / 64) * 256;
        float4 z = make_float4(0.f, 0.f, 0.f, 0.f);
        float4* den4 = (float4*)g_den;
        for (int i = gtid; i < (NUM_R * NT_NODES * NH) / 4; i += gstride) den4[i] = z;
        float4* t4 = (float4*)g_t;
        for (int i = gtid; i < (N_NODES * D) / 4; i += gstride) t4[i] = z;
        for (int i = gtid; i < N_NODES; i += gstride) g_mask[i] = 0ull;
    }

    const float* Wp[3] = { Wk + t * D * D, Wq + t * D * D, Wv + t * D * D };
    const float* bp[3] = { bk + t * D,     bq + t * D,     bv + t * D };
    float* op[3] = { g_k, g_q, g_v };

    // prefetch W chunk 0
    float4 wt0, wt1;
    {
        const float4* wg = (const float4*)Wp[0];
        wt0 = wg[tid]; wt1 = wg[tid + 256];
    }
    {
        float4* xs4 = (float4*)xs;
        #pragma unroll
        for (int i = 0; i < 8; i++) xs4[tid + i * 256] = xtmp[i];
    }

    int col = (tid & 31) * 4;
    int row = (tid >> 5) * 8;
    int newcol = ((col >> 2) & 3) * 32 + (col >> 4) * 4;   // swizzled target
    double acc[8][2];
    #pragma unroll
    for (int i = 0; i < 8; i++) { acc[i][0] = 0.0; acc[i][1] = 0.0; }

    for (int it = 0; it < 24; it++) {
        __syncthreads();
        float4* ws4 = (float4*)ws;
        ws4[tid] = wt0;
        ws4[tid + 256] = wt1;
        __syncthreads();
        if (it < 23) {                       // prefetch next chunk (overlaps compute)
            int p2 = (it + 1) >> 3, kc2 = (it + 1) & 7;
            const float4* wg = (const float4*)(Wp[p2] + kc2 * 16 * D);
            wt0 = wg[tid]; wt1 = wg[tid + 256];
        }
        int kc = it & 7;
        double2 wreg[16];
        #pragma unroll
        for (int kk = 0; kk < 16; kk++)
            wreg[kk] = *(const double2*)&ws[kk * D + col];
        #pragma unroll
        for (int i = 0; i < 8; i++) {
            const float4* xr = (const float4*)&xs[(row + i) * D + kc * 16];
            float4 xa = xr[0], xb = xr[1], xc = xr[2], xd = xr[3];
            #pragma unroll
            for (int kk = 0; kk < 16; kk++) {
                double xv2 = splat2(fcomp16(xa, xb, xc, xd, kk));
                fma2(acc[i][0], xv2, wreg[kk].x);
                fma2(acc[i][1], xv2, wreg[kk].y);
            }
        }
        if (kc == 7) {
            int p = it >> 3;
            float4 bb = *(const float4*)&bp[p][col];
            float* o = op[p];
            #pragma unroll
            for (int i = 0; i < 8; i++) {
                float2 p0 = unpack2(acc[i][0]);
                float2 p1 = unpack2(acc[i][1]);
                float4 rr = make_float4(p0.x + bb.x, p0.y + bb.y, p1.x + bb.z, p1.y + bb.w);
                *(float4*)&o[(size_t)(node0 + row + i) * D + newcol] = rr;
                acc[i][0] = 0.0; acc[i][1] = 0.0;
            }
        }
    }
}

// ---------------- edge scores -----------------------------------------------
// 2 edges/thread, kt-form, swizzled gathers. na dots computed inline. src/dst
// pairs loaded as int2 (e0 always even, e1=e0+1 always valid since EPR even).
__global__ __launch_bounds__(256, 4) void edge_score_kernel(
    const int* __restrict__ src, const int* __restrict__ dst,
    const float* __restrict__ rel_att, const float* __restrict__ rel_pri,
    const float* __restrict__ nta, const float* __restrict__ nta1,
    const float* __restrict__ weight, const float* __restrict__ attn_w)
{
    __shared__ float4 ratt4[16 * 4 * NH];   // [dd][f4][h]
    __shared__ float pri[NH];
    __shared__ float4 wq4[4];               // wq, chunk-packed (16 floats)
    __shared__ float wks[16];               // wk scalars
    int r = blockIdx.y;
    int tid = threadIdx.x;
    {
        float* ratt = (float*)ratt4;
        #pragma unroll
        for (int it = 0; it < 8; it++) {
            int i = tid + it * 256;                       // = h*256 + dd*16 + f
            int hh = i >> 8, dd = (i >> 4) & 15, ff = i & 15;
            ratt[((dd * 4 + (ff >> 2)) * NH + hh) * 4 + (ff & 3)] = rel_att[r * 2048 + i];
        }
    }
    if (tid < NH) pri[tid] = rel_pri[r * NH + tid] * 0.25f;  // fold 1/sqrt(16)
    if (tid >= 32 && tid < 48) ((float*)wq4)[tid - 32] = attn_w[tid - 32];
    if (tid >= 48 && tid < 64) wks[tid - 48] = attn_w[tid - 32];
    __syncthreads();

    int h = tid & 7;
    int e0 = blockIdx.x * 64 + (tid >> 3) * 2;
    if (e0 >= EPR) return;
    int e1 = e0 + 1;                         // always < EPR (EPR even, e0 even)

    int2 sp = *(const int2*)&src[r * EPR + e0];
    int2 dp = *(const int2*)&dst[r * EPR + e0];
    int s0 = sp.x, s1 = sp.y, d0 = dp.x, d1 = dp.y;

    const double2* A2 = (const double2*)ratt4;
    double kt0[8], kt1[8];
    #pragma unroll
    for (int p = 0; p < 8; p++) { kt0[p] = 0.0; kt1[p] = 0.0; }
    float kw0 = 0.f, kw1 = 0.f;

    const float4* kb0 = (const float4*)(g_k + (size_t)s0 * D);
    const float4* kb1 = (const float4*)(g_k + (size_t)s1 * D);
    #pragma unroll
    for (int dh = 0; dh < 2; dh++) {
        float4 ka0 = kb0[(dh * 2) * 8 + h], kc0 = kb0[(dh * 2 + 1) * 8 + h];
        float4 ka1 = kb1[(dh * 2) * 8 + h], kc1 = kb1[(dh * 2 + 1) * 8 + h];
        #pragma unroll
        for (int di = 0; di < 8; di++) {
            int dd = dh * 8 + di;
            float k0f = fcomp(ka0, kc0, di);
            float k1f = fcomp(ka1, kc1, di);
            float wkd = wks[dd];
            kw0 = fmaf(wkd, k0f, kw0);
            kw1 = fmaf(wkd, k1f, kw1);
            double k0s = splat2(k0f);
            double k1s = splat2(k1f);
            #pragma unroll
            for (int f4 = 0; f4 < 4; f4++) {
                double2 m = A2[(dd * 4 + f4) * NH + h];   // shared by both edges
                fma2(kt0[2 * f4],     k0s, m.x);
                fma2(kt0[2 * f4 + 1], k0s, m.y);
                fma2(kt1[2 * f4],     k1s, m.x);
                fma2(kt1[2 * f4 + 1], k1s, m.y);
            }
        }
    }

    // dot with q (loaded only now, after k registers die); also q.wq inline
    double s20 = 0.0, s21 = 0.0, qa0 = 0.0, qa1 = 0.0;
    {
        const double2* qb0 = (const double2*)(g_q + (size_t)d0 * D);
        const double2* qb1 = (const double2*)(g_q + (size_t)d1 * D);
        const double2* WQ = (const double2*)wq4;
        #pragma unroll
        for (int j = 0; j < 4; j++) {
            double2 wq = WQ[j];
            double2 q0 = qb0[j * 8 + h];                  // chunk j of head h
            fma2(s20, kt0[2 * j],     q0.x);
            fma2(s20, kt0[2 * j + 1], q0.y);
            fma2(qa0, wq.x, q0.x);
            fma2(qa0, wq.y, q0.y);
            double2 q1 = qb1[j * 8 + h];
            fma2(s21, kt1[2 * j],     q1.x);
            fma2(s21, kt1[2 * j + 1], q1.y);
            fma2(qa1, wq.x, q1.x);
            fma2(qa1, wq.y, q1.y);
        }
    }
    float prh = pri[h];
    float2 u0 = unpack2(s20);
    float a0 = (u0.x + u0.y) * prh;
    float2 u1 = unpack2(s21);
    float a1 = (u1.x + u1.y) * prh;
    float2 w0 = unpack2(qa0);
    float qw0 = w0.x + w0.y;
    float2 w1 = unpack2(qa1);
    float qw1 = w1.x + w1.y;

    int snt = src_nt(r), dnt = dst_nt(r);
    float ntaS = nta[snt], ntaD = nta1[dnt];
    float beta = 1.f / (1.f + __expf(-weight[0]));
    {
        float na = ntaD * qw0 + ntaS * kw0;
        na = na > 0.f ? na : 0.01f * na;
        float ev = __expf(a0 + beta * na);
        g_e[((size_t)r * EPR + e0) * NH + h] = ev;
        atomicAdd(&g_den[((size_t)r * NT_NODES + (d0 - dnt * NT_NODES)) * NH + h], ev);
        if (h == 0) atomicOr(&g_mask[d0], 1ull << r);
    }
    {
        float na = ntaD * qw1 + ntaS * kw1;
        na = na > 0.f ? na : 0.01f * na;
        float ev = __expf(a1 + beta * na);
        g_e[((size_t)r * EPR + e1) * NH + h] = ev;
        atomicAdd(&g_den[((size_t)r * NT_NODES + (d1 - dnt * NT_NODES)) * NH + h], ev);
        if (h == 0) atomicOr(&g_mask[d1], 1ull << r);
    }
}

// ---------------- invert denominators, folding 1/nrel (x4 vectorized) -------
__global__ void deninv_kernel() {
    int i4 = blockIdx.x * blockDim.x + threadIdx.x;
    if (i4 >= (NUM_R * NT_NODES * NH) / 4) return;
    int idx = i4 * 4;
    int r = idx / (NT_NODES * NH);
    int rem = idx - r * (NT_NODES * NH);
    int dl = rem / NH;
    int d = dst_nt(r) * NT_NODES + dl;
    int c = __popcll(g_mask[d]);
    float cf = (float)(c > 0 ? c : 1);
    float4 den = *(float4*)&g_den[idx];
    den.x = den.x > 0.f ? __fdividef(1.f, den.x * cf) : 0.f;
    den.y = den.y > 0.f ? __fdividef(1.f, den.y * cf) : 0.f;
    den.z = den.z > 0.f ? __fdividef(1.f, den.z * cf) : 0.f;
    den.w = den.w > 0.f ? __fdividef(1.f, den.w * cf) : 0.f;
    *(float4*)&g_den[idx] = den;
}

// ---------------- message transform + weighted scatter into t ---------------
// 2 edges/thread; swizzled v gathers and t scatters. e/den loads hoisted
// before the transform loop so their latency overlaps the FMA work.
__global__ __launch_bounds__(256, 4) void edge_accum_kernel(
    const int* __restrict__ src, const int* __restrict__ dst,
    const float* __restrict__ rel_msg)
{
    __shared__ float4 rm4[16 * 4 * NH];   // [dd][f4][h]
    int r = blockIdx.y;
    int tid = threadIdx.x;
    {
        float* rm = (float*)rm4;
        #pragma unroll
        for (int it = 0; it < 8; it++) {
            int i = tid + it * 256;
            int hh = i >> 8, dd = (i >> 4) & 15, ff = i & 15;
            rm[((dd * 4 + (ff >> 2)) * NH + hh) * 4 + (ff & 3)] = rel_msg[r * 2048 + i];
        }
    }
    __syncthreads();

    int h = tid & 7;
    int e0 = blockIdx.x * 64 + (tid >> 3) * 2;
    if (e0 >= EPR) return;
    int e1 = e0 + 1;                         // always < EPR (EPR even, e0 even)
    int dnt = dst_nt(r);

    int2 sp = *(const int2*)&src[r * EPR + e0];
    int2 dp = *(const int2*)&dst[r * EPR + e0];
    int s0 = sp.x, s1 = sp.y, d0 = dp.x, d1 = dp.y;

    // hoisted: softmax weight operands (consumed after the transform loop)
    float ew0 = g_e[((size_t)r * EPR + e0) * NH + h];
    float ew1 = g_e[((size_t)r * EPR + e1) * NH + h];
    float dn0 = g_den[((size_t)r * NT_NODES + (d0 - dnt * NT_NODES)) * NH + h];
    float dn1 = g_den[((size_t)r * NT_NODES + (d1 - dnt * NT_NODES)) * NH + h];

    const double2* M2 = (const double2*)rm4;
    double acc0[8], acc1[8];
    #pragma unroll
    for (int p = 0; p < 8; p++) { acc0[p] = 0.0; acc1[p] = 0.0; }

    const float4* vb0 = (const float4*)(g_v + (size_t)s0 * D);
    const float4* vb1 = (const float4*)(g_v + (size_t)s1 * D);
    #pragma unroll
    for (int dh = 0; dh < 2; dh++) {
        float4 va0 = vb0[(dh * 2) * 8 + h], vc0 = vb0[(dh * 2 + 1) * 8 + h];
        float4 va1 = vb1[(dh * 2) * 8 + h], vc1 = vb1[(dh * 2 + 1) * 8 + h];
        #pragma unroll
        for (int di = 0; di < 8; di++) {
            int dd = dh * 8 + di;
            double v0s = splat2(fcomp(va0, vc0, di));
            double v1s = splat2(fcomp(va1, vc1, di));
            #pragma unroll
            for (int f4 = 0; f4 < 4; f4++) {
                double2 m = M2[(dd * 4 + f4) * NH + h];   // shared by both edges
                fma2(acc0[2 * f4],     v0s, m.x);
                fma2(acc0[2 * f4 + 1], v0s, m.y);
                fma2(acc1[2 * f4],     v1s, m.x);
                fma2(acc1[2 * f4 + 1], v1s, m.y);
            }
        }
    }

    double w0s = splat2(ew0 * dn0), w1s = splat2(ew1 * dn1);
    #pragma unroll
    for (int p = 0; p < 8; p++) { mul2(acc0[p], w0s); mul2(acc1[p], w1s); }

    float* tp0 = g_t + (size_t)d0 * D + h * 4;
    #pragma unroll
    for (int f4 = 0; f4 < 4; f4++) {
        float2 o0 = unpack2(acc0[2 * f4]);
        float2 o1 = unpack2(acc0[2 * f4 + 1]);
        asm volatile("red.global.add.v4.f32 [%0], {%1, %2, %3, %4};"
                     :: "l"(tp0 + f4 * 32),
                        "f"(o0.x), "f"(o0.y), "f"(o1.x), "f"(o1.y)
                     : "memory");
    }
    {
        float* tp1 = g_t + (size_t)d1 * D + h * 4;
        #pragma unroll
        for (int f4 = 0; f4 < 4; f4++) {
            float2 o0 = unpack2(acc1[2 * f4]);
            float2 o1 = unpack2(acc1[2 * f4 + 1]);
            asm volatile("red.global.add.v4.f32 [%0], {%1, %2, %3, %4};"
                         :: "l"(tp1 + f4 * 32),
                            "f"(o0.x), "f"(o0.y), "f"(o1.x), "f"(o1.y)
                         : "memory");
        }
    }
}

// ---------------- final typed projection + gated skip ------------------------
// g_t (swizzled) -> SMEM standard order; GEMM with W-chunk register prefetch.
__global__ __launch_bounds__(256) void final_kernel(
    const float* __restrict__ x,
    const float* __restrict__ Wa, const float* __restrict__ ba,
    const float* __restrict__ skip, float* __restrict__ out)
{
    __shared__ float xs[64 * D];
    __shared__ float ws[16 * D];
    int node0 = blockIdx.x * 64;
    int t = node0 / NT_NODES;
    int tid = threadIdx.x;

    float4 ttmp[8];
    {
        const float4* tg = (const float4*)(g_t + (size_t)node0 * D);
        #pragma unroll
        for (int i = 0; i < 8; i++) ttmp[i] = tg[tid + i * 256];
    }
    const float* Wp = Wa + t * D * D;
    float4 wt0, wt1;
    {
        const float4* wg = (const float4*)Wp;
        wt0 = wg[tid]; wt1 = wg[tid + 256];
    }
    {
        float4* xs4 = (float4*)xs;
        #pragma unroll
        for (int i = 0; i < 8; i++) {
            int idx = tid + i * 256;
            int nl = idx >> 5, c = idx & 31;           // swizzled chunk c = j*8+h
            int stdc = ((c & 7) << 2) + (c >> 3);      // std chunk = h*4+j
            xs4[nl * 32 + stdc] = ttmp[i];
        }
    }

    int col = (tid & 31) * 4;
    int row = (tid >> 5) * 8;
    double acc[8][2];
    #pragma unroll
    for (int i = 0; i < 8; i++) { acc[i][0] = 0.0; acc[i][1] = 0.0; }

    for (int kc = 0; kc < 8; kc++) {
        __syncthreads();
        float4* ws4 = (float4*)ws;
        ws4[tid] = wt0;
        ws4[tid + 256] = wt1;
        __syncthreads();
        if (kc < 7) {                        // prefetch next chunk
            const float4* wg = (const float4*)(Wp + (kc + 1) * 16 * D);
            wt0 = wg[tid]; wt1 = wg[tid + 256];
        }
        double2 wreg[16];
        #pragma unroll
        for (int kk = 0; kk < 16; kk++)
            wreg[kk] = *(const double2*)&ws[kk * D + col];
        #pragma unroll
        for (int i = 0; i < 8; i++) {
            const float4* xr = (const float4*)&xs[(row + i) * D + kc * 16];
            float4 xa = xr[0], xb = xr[1], xc = xr[2], xd = xr[3];
            #pragma unroll
            for (int kk = 0; kk < 16; kk++) {
                double xv2 = splat2(fcomp16(xa, xb, xc, xd, kk));
                fma2(acc[i][0], xv2, wreg[kk].x);
                fma2(acc[i][1], xv2, wreg[kk].y);
            }
        }
    }
    float alpha = 1.f / (1.f + __expf(-skip[t]));
    float onema = 1.f - alpha;
    float4 bb = *(const float4*)&ba[t * D + col];
    #pragma unroll
    for (int i = 0; i < 8; i++) {
        size_t off = (size_t)(node0 + row + i) * D + col;
        float4 xv = *(const float4*)&x[off];
        float2 p0 = unpack2(acc[i][0]);
        float2 p1 = unpack2(acc[i][1]);
        float4 rr;
        rr.x = (p0.x + bb.x) * alpha + xv.x * onema;
        rr.y = (p0.y + bb.y) * alpha + xv.y * onema;
        rr.z = (p1.x + bb.z) * alpha + xv.z * onema;
        rr.w = (p1.y + bb.w) * alpha + xv.w * onema;
        *(float4*)&out[off] = rr;
    }
}

// ---------------- launch ------------------------------------------------------
extern "C" void kernel_launch(void* const* d_in, const int* in_sizes, int n_in,
                              void* d_out, int out_size)
{
    const float* x       = (const float*)d_in[0];
    const int*   src     = (const int*)  d_in[1];
    const int*   dst     = (const int*)  d_in[2];
    const float* Wk      = (const float*)d_in[3];
    const float* bk      = (const float*)d_in[4];
    const float* Wq      = (const float*)d_in[5];
    const float* bq      = (const float*)d_in[6];
    const float* Wv      = (const float*)d_in[7];
    const float* bv      = (const float*)d_in[8];
    const float* Wa      = (const float*)d_in[9];
    const float* ba      = (const float*)d_in[10];
    const float* rel_att = (const float*)d_in[11];
    const float* rel_msg = (const float*)d_in[12];
    const float* rel_pri = (const float*)d_in[13];
    const float* nta     = (const float*)d_in[14];
    const float* nta1    = (const float*)d_in[15];
    const float* skip    = (const float*)d_in[16];
    const float* weight  = (const float*)d_in[17];
    const float* attn_w  = (const float*)d_in[18];
    float* out = (float*)d_out;

    proj3_kernel<<<N_NODES / 64, 256>>>(x, Wk, bk, Wq, bq, Wv, bv);
    edge_score_kernel<<<dim3(EBLK2, NUM_R), 256>>>(src, dst, rel_att, rel_pri, nta, nta1, weight, attn_w);
    deninv_kernel<<<((NUM_R * NT_NODES * NH) / 4 + 255) / 256, 256>>>();
    edge_accum_kernel<<<dim3(EBLK2, NUM_R), 256>>>(src, dst, rel_msg);
    final_kernel<<<N_NODES / 64, 256>>>(x, Wa, ba, skip, out);
}

// round 16
// speedup vs baseline: 1.0407x; 1.0126x over previous
#include <cuda_runtime.h>
#include <math.h>

#define N_NODES   24000
#define NT_NODES  8000
#define NUM_T     3
#define NUM_R     34
#define EPR       10000
#define NH        8
#define DKQ       16
#define D         128
#define EBLK5     79             // ceil(10000/128): edge blocks (512 thr, 2 edges/thread)

// Swizzled node-feature layout for k/q/v/t:
//   element (h, f) of a node lives at  chunk j = f/4, offset  j*32 + h*4 + (f%4)
// so one head's j-th float4 for the 8 heads of a warp-group is 128B contiguous.

// ---------------- scratch (device globals; no allocation allowed) ----------
__device__ float g_k[N_NODES * D];
__device__ float g_q[N_NODES * D];
__device__ float g_v[N_NODES * D];
__device__ float g_e[NUM_R * EPR * NH];          // exp(score) per edge/head
__device__ float g_den[NUM_R * NT_NODES * NH];   // softmax denom -> inverted in-place
__device__ unsigned long long g_mask[N_NODES];   // relation bitmask per dst node
__device__ float g_t[N_NODES * D];               // aggregated messages (swizzled)

// relation -> node-type maps (compile-time formulas from reference)
__device__ __forceinline__ int src_nt(int r) { return r <= 9 ? 0 : (r <= 21 ? 1 : 2); }
__device__ __forceinline__ int dst_nt(int r) {
    if (r <= 2 || (r >= 10 && r <= 13) || (r >= 22 && r <= 24)) return 0;
    if ((r >= 3 && r <= 6) || (r >= 14 && r <= 17) || (r >= 25 && r <= 28)) return 1;
    return 2;
}

// ---------------- packed f32x2 helpers (Blackwell FFMA2) --------------------
__device__ __forceinline__ double splat2(float x) {
    double r; asm("mov.b64 %0, {%1, %1};" : "=d"(r) : "f"(x)); return r;
}
__device__ __forceinline__ void fma2(double& d, double a, double b) {
    asm("fma.rn.f32x2 %0, %1, %2, %0;" : "+d"(d) : "d"(a), "d"(b));
}
__device__ __forceinline__ void mul2(double& d, double a) {
    asm("mul.rn.f32x2 %0, %0, %1;" : "+d"(d) : "d"(a));
}
__device__ __forceinline__ float2 unpack2(double d) {
    float lo, hi; asm("mov.b64 {%0, %1}, %2;" : "=f"(lo), "=f"(hi) : "d"(d));
    return make_float2(lo, hi);
}
__device__ __forceinline__ float fcomp(float4 a, float4 b, int i) {
    switch (i) {
        case 0: return a.x; case 1: return a.y; case 2: return a.z; case 3: return a.w;
        case 4: return b.x; case 5: return b.y; case 6: return b.z; default: return b.w;
    }
}
__device__ __forceinline__ float fcomp16(float4 a, float4 b, float4 c, float4 d, int i) {
    return i < 8 ? fcomp(a, b, i) : fcomp(c, d, i - 8);
}

// ---------------- typed K/Q/V projections (3 dense GEMMs per type) ----------
// Flattened (p,kc) loop with register prefetch of the next W chunk so the W
// LDG latency overlaps compute. Prologue zeroes g_den/g_t/g_mask while the x
// LDGs are in flight. Output stored swizzled: col -> (col%16)/4*32+(col/16)*4.
__global__ __launch_bounds__(256) void proj3_kernel(
    const float* __restrict__ x,
    const float* __restrict__ Wk, const float* __restrict__ bk,
    const float* __restrict__ Wq, const float* __restrict__ bq,
    const float* __restrict__ Wv, const float* __restrict__ bv)
{
    __shared__ float xs[64 * D];
    __shared__ float ws[16 * D];
    int node0 = blockIdx.x * 64;
    int t = node0 / NT_NODES;
    int tid = threadIdx.x;

    // issue x loads first
    float4 xtmp[8];
    {
        const float4* xg = (const float4*)(x + (size_t)node0 * D);
        #pragma unroll
        for (int i = 0; i < 8; i++) xtmp[i] = xg[tid + i * 256];
    }

    // zero scratch (grid-stride) while x loads are in flight
    {
        int gtid = blockIdx.x * 256 + tid;
        int gstride = (N_NODES / 64) * 256;
        float4 z = make_float4(0.f, 0.f, 0.f, 0.f);
        float4* den4 = (float4*)g_den;
        for (int i = gtid; i < (NUM_R * NT_NODES * NH) / 4; i += gstride) den4[i] = z;
        float4* t4 = (float4*)g_t;
        for (int i = gtid; i < (N_NODES * D) / 4; i += gstride) t4[i] = z;
        for (int i = gtid; i < N_NODES; i += gstride) g_mask[i] = 0ull;
    }

    const float* Wp[3] = { Wk + t * D * D, Wq + t * D * D, Wv + t * D * D };
    const float* bp[3] = { bk + t * D,     bq + t * D,     bv + t * D };
    float* op[3] = { g_k, g_q, g_v };

    // prefetch W chunk 0
    float4 wt0, wt1;
    {
        const float4* wg = (const float4*)Wp[0];
        wt0 = wg[tid]; wt1 = wg[tid + 256];
    }
    {
        float4* xs4 = (float4*)xs;
        #pragma unroll
        for (int i = 0; i < 8; i++) xs4[tid + i * 256] = xtmp[i];
    }

    int col = (tid & 31) * 4;
    int row = (tid >> 5) * 8;
    int newcol = ((col >> 2) & 3) * 32 + (col >> 4) * 4;   // swizzled target
    double acc[8][2];
    #pragma unroll
    for (int i = 0; i < 8; i++) { acc[i][0] = 0.0; acc[i][1] = 0.0; }

    for (int it = 0; it < 24; it++) {
        __syncthreads();
        float4* ws4 = (float4*)ws;
        ws4[tid] = wt0;
        ws4[tid + 256] = wt1;
        __syncthreads();
        if (it < 23) {                       // prefetch next chunk (overlaps compute)
            int p2 = (it + 1) >> 3, kc2 = (it + 1) & 7;
            const float4* wg = (const float4*)(Wp[p2] + kc2 * 16 * D);
            wt0 = wg[tid]; wt1 = wg[tid + 256];
        }
        int kc = it & 7;
        double2 wreg[16];
        #pragma unroll
        for (int kk = 0; kk < 16; kk++)
            wreg[kk] = *(const double2*)&ws[kk * D + col];
        #pragma unroll
        for (int i = 0; i < 8; i++) {
            const float4* xr = (const float4*)&xs[(row + i) * D + kc * 16];
            float4 xa = xr[0], xb = xr[1], xc = xr[2], xd = xr[3];
            #pragma unroll
            for (int kk = 0; kk < 16; kk++) {
                double xv2 = splat2(fcomp16(xa, xb, xc, xd, kk));
                fma2(acc[i][0], xv2, wreg[kk].x);
                fma2(acc[i][1], xv2, wreg[kk].y);
            }
        }
        if (kc == 7) {
            int p = it >> 3;
            float4 bb = *(const float4*)&bp[p][col];
            float* o = op[p];
            #pragma unroll
            for (int i = 0; i < 8; i++) {
                float2 p0 = unpack2(acc[i][0]);
                float2 p1 = unpack2(acc[i][1]);
                float4 rr = make_float4(p0.x + bb.x, p0.y + bb.y, p1.x + bb.z, p1.y + bb.w);
                *(float4*)&o[(size_t)(node0 + row + i) * D + newcol] = rr;
                acc[i][0] = 0.0; acc[i][1] = 0.0;
            }
        }
    }
}

// ---------------- edge scores -----------------------------------------------
// 512 threads = 128 edges/block (halves per-relation block count and matrix
// fill cost). 2 edges/thread, kt-form, swizzled gathers, inline na dots.
__global__ __launch_bounds__(512, 2) void edge_score_kernel(
    const int* __restrict__ src, const int* __restrict__ dst,
    const float* __restrict__ rel_att, const float* __restrict__ rel_pri,
    const float* __restrict__ nta, const float* __restrict__ nta1,
    const float* __restrict__ weight, const float* __restrict__ attn_w)
{
    __shared__ float4 ratt4[16 * 4 * NH];   // [dd][f4][h]
    __shared__ float pri[NH];
    __shared__ float4 wq4[4];               // wq, chunk-packed (16 floats)
    __shared__ float wks[16];               // wk scalars
    int r = blockIdx.y;
    int tid = threadIdx.x;
    {
        float* ratt = (float*)ratt4;
        #pragma unroll
        for (int it = 0; it < 4; it++) {
            int i = tid + it * 512;                       // = h*256 + dd*16 + f
            int hh = i >> 8, dd = (i >> 4) & 15, ff = i & 15;
            ratt[((dd * 4 + (ff >> 2)) * NH + hh) * 4 + (ff & 3)] = rel_att[r * 2048 + i];
        }
    }
    if (tid < NH) pri[tid] = rel_pri[r * NH + tid] * 0.25f;  // fold 1/sqrt(16)
    if (tid >= 32 && tid < 48) ((float*)wq4)[tid - 32] = attn_w[tid - 32];
    if (tid >= 48 && tid < 64) wks[tid - 48] = attn_w[tid - 32];
    __syncthreads();

    int h = tid & 7;
    int e0 = blockIdx.x * 128 + (tid >> 3) * 2;
    if (e0 >= EPR) return;
    int e1 = e0 + 1;                         // always < EPR (EPR even, e0 even)

    int2 sp = *(const int2*)&src[r * EPR + e0];
    int2 dp = *(const int2*)&dst[r * EPR + e0];
    int s0 = sp.x, s1 = sp.y, d0 = dp.x, d1 = dp.y;

    const double2* A2 = (const double2*)ratt4;
    double kt0[8], kt1[8];
    #pragma unroll
    for (int p = 0; p < 8; p++) { kt0[p] = 0.0; kt1[p] = 0.0; }
    float kw0 = 0.f, kw1 = 0.f;

    const float4* kb0 = (const float4*)(g_k + (size_t)s0 * D);
    const float4* kb1 = (const float4*)(g_k + (size_t)s1 * D);
    #pragma unroll
    for (int dh = 0; dh < 2; dh++) {
        float4 ka0 = kb0[(dh * 2) * 8 + h], kc0 = kb0[(dh * 2 + 1) * 8 + h];
        float4 ka1 = kb1[(dh * 2) * 8 + h], kc1 = kb1[(dh * 2 + 1) * 8 + h];
        #pragma unroll
        for (int di = 0; di < 8; di++) {
            int dd = dh * 8 + di;
            float k0f = fcomp(ka0, kc0, di);
            float k1f = fcomp(ka1, kc1, di);
            float wkd = wks[dd];
            kw0 = fmaf(wkd, k0f, kw0);
            kw1 = fmaf(wkd, k1f, kw1);
            double k0s = splat2(k0f);
            double k1s = splat2(k1f);
            #pragma unroll
            for (int f4 = 0; f4 < 4; f4++) {
                double2 m = A2[(dd * 4 + f4) * NH + h];   // shared by both edges
                fma2(kt0[2 * f4],     k0s, m.x);
                fma2(kt0[2 * f4 + 1], k0s, m.y);
                fma2(kt1[2 * f4],     k1s, m.x);
                fma2(kt1[2 * f4 + 1], k1s, m.y);
            }
        }
    }

    // dot with q (loaded only now, after k registers die); also q.wq inline
    double s20 = 0.0, s21 = 0.0, qa0 = 0.0, qa1 = 0.0;
    {
        const double2* qb0 = (const double2*)(g_q + (size_t)d0 * D);
        const double2* qb1 = (const double2*)(g_q + (size_t)d1 * D);
        const double2* WQ = (const double2*)wq4;
        #pragma unroll
        for (int j = 0; j < 4; j++) {
            double2 wq = WQ[j];
            double2 q0 = qb0[j * 8 + h];                  // chunk j of head h
            fma2(s20, kt0[2 * j],     q0.x);
            fma2(s20, kt0[2 * j + 1], q0.y);
            fma2(qa0, wq.x, q0.x);
            fma2(qa0, wq.y, q0.y);
            double2 q1 = qb1[j * 8 + h];
            fma2(s21, kt1[2 * j],     q1.x);
            fma2(s21, kt1[2 * j + 1], q1.y);
            fma2(qa1, wq.x, q1.x);
            fma2(qa1, wq.y, q1.y);
        }
    }
    float prh = pri[h];
    float2 u0 = unpack2(s20);
    float a0 = (u0.x + u0.y) * prh;
    float2 u1 = unpack2(s21);
    float a1 = (u1.x + u1.y) * prh;
    float2 w0 = unpack2(qa0);
    float qw0 = w0.x + w0.y;
    float2 w1 = unpack2(qa1);
    float qw1 = w1.x + w1.y;

    int snt = src_nt(r), dnt = dst_nt(r);
    float ntaS = nta[snt], ntaD = nta1[dnt];
    float beta = 1.f / (1.f + __expf(-weight[0]));
    {
        float na = ntaD * qw0 + ntaS * kw0;
        na = na > 0.f ? na : 0.01f * na;
        float ev = __expf(a0 + beta * na);
        g_e[((size_t)r * EPR + e0) * NH + h] = ev;
        atomicAdd(&g_den[((size_t)r * NT_NODES + (d0 - dnt * NT_NODES)) * NH + h], ev);
        if (h == 0) atomicOr(&g_mask[d0], 1ull << r);
    }
    {
        float na = ntaD * qw1 + ntaS * kw1;
        na = na > 0.f ? na : 0.01f * na;
        float ev = __expf(a1 + beta * na);
        g_e[((size_t)r * EPR + e1) * NH + h] = ev;
        atomicAdd(&g_den[((size_t)r * NT_NODES + (d1 - dnt * NT_NODES)) * NH + h], ev);
        if (h == 0) atomicOr(&g_mask[d1], 1ull << r);
    }
}

// ---------------- invert denominators, folding 1/nrel (x4 vectorized) -------
__global__ void deninv_kernel() {
    int i4 = blockIdx.x * blockDim.x + threadIdx.x;
    if (i4 >= (NUM_R * NT_NODES * NH) / 4) return;
    int idx = i4 * 4;
    int r = idx / (NT_NODES * NH);
    int rem = idx - r * (NT_NODES * NH);
    int dl = rem / NH;
    int d = dst_nt(r) * NT_NODES + dl;
    int c = __popcll(g_mask[d]);
    float cf = (float)(c > 0 ? c : 1);
    float4 den = *(float4*)&g_den[idx];
    den.x = den.x > 0.f ? __fdividef(1.f, den.x * cf) : 0.f;
    den.y = den.y > 0.f ? __fdividef(1.f, den.y * cf) : 0.f;
    den.z = den.z > 0.f ? __fdividef(1.f, den.z * cf) : 0.f;
    den.w = den.w > 0.f ? __fdividef(1.f, den.w * cf) : 0.f;
    *(float4*)&g_den[idx] = den;
}

// ---------------- message transform + weighted scatter into t ---------------
// 512 threads = 128 edges/block; 2 edges/thread; swizzled v gathers and t
// scatters. e/den loads hoisted before the transform loop.
__global__ __launch_bounds__(512, 2) void edge_accum_kernel(
    const int* __restrict__ src, const int* __restrict__ dst,
    const float* __restrict__ rel_msg)
{
    __shared__ float4 rm4[16 * 4 * NH];   // [dd][f4][h]
    int r = blockIdx.y;
    int tid = threadIdx.x;
    {
        float* rm = (float*)rm4;
        #pragma unroll
        for (int it = 0; it < 4; it++) {
            int i = tid + it * 512;
            int hh = i >> 8, dd = (i >> 4) & 15, ff = i & 15;
            rm[((dd * 4 + (ff >> 2)) * NH + hh) * 4 + (ff & 3)] = rel_msg[r * 2048 + i];
        }
    }
    __syncthreads();

    int h = tid & 7;
    int e0 = blockIdx.x * 128 + (tid >> 3) * 2;
    if (e0 >= EPR) return;
    int e1 = e0 + 1;                         // always < EPR (EPR even, e0 even)
    int dnt = dst_nt(r);

    int2 sp = *(const int2*)&src[r * EPR + e0];
    int2 dp = *(const int2*)&dst[r * EPR + e0];
    int s0 = sp.x, s1 = sp.y, d0 = dp.x, d1 = dp.y;

    // hoisted: softmax weight operands (consumed after the transform loop)
    float ew0 = g_e[((size_t)r * EPR + e0) * NH + h];
    float ew1 = g_e[((size_t)r * EPR + e1) * NH + h];
    float dn0 = g_den[((size_t)r * NT_NODES + (d0 - dnt * NT_NODES)) * NH + h];
    float dn1 = g_den[((size_t)r * NT_NODES + (d1 - dnt * NT_NODES)) * NH + h];

    const double2* M2 = (const double2*)rm4;
    double acc0[8], acc1[8];
    #pragma unroll
    for (int p = 0; p < 8; p++) { acc0[p] = 0.0; acc1[p] = 0.0; }

    const float4* vb0 = (const float4*)(g_v + (size_t)s0 * D);
    const float4* vb1 = (const float4*)(g_v + (size_t)s1 * D);
    #pragma unroll
    for (int dh = 0; dh < 2; dh++) {
        float4 va0 = vb0[(dh * 2) * 8 + h], vc0 = vb0[(dh * 2 + 1) * 8 + h];
        float4 va1 = vb1[(dh * 2) * 8 + h], vc1 = vb1[(dh * 2 + 1) * 8 + h];
        #pragma unroll
        for (int di = 0; di < 8; di++) {
            int dd = dh * 8 + di;
            double v0s = splat2(fcomp(va0, vc0, di));
            double v1s = splat2(fcomp(va1, vc1, di));
            #pragma unroll
            for (int f4 = 0; f4 < 4; f4++) {
                double2 m = M2[(dd * 4 + f4) * NH + h];   // shared by both edges
                fma2(acc0[2 * f4],     v0s, m.x);
                fma2(acc0[2 * f4 + 1], v0s, m.y);
                fma2(acc1[2 * f4],     v1s, m.x);
                fma2(acc1[2 * f4 + 1], v1s, m.y);
            }
        }
    }

    double w0s = splat2(ew0 * dn0), w1s = splat2(ew1 * dn1);
    #pragma unroll
    for (int p = 0; p < 8; p++) { mul2(acc0[p], w0s); mul2(acc1[p], w1s); }

    float* tp0 = g_t + (size_t)d0 * D + h * 4;
    #pragma unroll
    for (int f4 = 0; f4 < 4; f4++) {
        float2 o0 = unpack2(acc0[2 * f4]);
        float2 o1 = unpack2(acc0[2 * f4 + 1]);
        asm volatile("red.global.add.v4.f32 [%0], {%1, %2, %3, %4};"
                     :: "l"(tp0 + f4 * 32),
                        "f"(o0.x), "f"(o0.y), "f"(o1.x), "f"(o1.y)
                     : "memory");
    }
    {
        float* tp1 = g_t + (size_t)d1 * D + h * 4;
        #pragma unroll
        for (int f4 = 0; f4 < 4; f4++) {
            float2 o0 = unpack2(acc1[2 * f4]);
            float2 o1 = unpack2(acc1[2 * f4 + 1]);
            asm volatile("red.global.add.v4.f32 [%0], {%1, %2, %3, %4};"
                         :: "l"(tp1 + f4 * 32),
                            "f"(o0.x), "f"(o0.y), "f"(o1.x), "f"(o1.y)
                         : "memory");
        }
    }
}

// ---------------- final typed projection + gated skip ------------------------
// g_t (swizzled) -> SMEM standard order; GEMM with W-chunk register prefetch.
__global__ __launch_bounds__(256) void final_kernel(
    const float* __restrict__ x,
    const float* __restrict__ Wa, const float* __restrict__ ba,
    const float* __restrict__ skip, float* __restrict__ out)
{
    __shared__ float xs[64 * D];
    __shared__ float ws[16 * D];
    int node0 = blockIdx.x * 64;
    int t = node0 / NT_NODES;
    int tid = threadIdx.x;

    float4 ttmp[8];
    {
        const float4* tg = (const float4*)(g_t + (size_t)node0 * D);
        #pragma unroll
        for (int i = 0; i < 8; i++) ttmp[i] = tg[tid + i * 256];
    }
    const float* Wp = Wa + t * D * D;
    float4 wt0, wt1;
    {
        const float4* wg = (const float4*)Wp;
        wt0 = wg[tid]; wt1 = wg[tid + 256];
    }
    {
        float4* xs4 = (float4*)xs;
        #pragma unroll
        for (int i = 0; i < 8; i++) {
            int idx = tid + i * 256;
            int nl = idx >> 5, c = idx & 31;           // swizzled chunk c = j*8+h
            int stdc = ((c & 7) << 2) + (c >> 3);      // std chunk = h*4+j
            xs4[nl * 32 + stdc] = ttmp[i];
        }
    }

    int col = (tid & 31) * 4;
    int row = (tid >> 5) * 8;
    double acc[8][2];
    #pragma unroll
    for (int i = 0; i < 8; i++) { acc[i][0] = 0.0; acc[i][1] = 0.0; }

    for (int kc = 0; kc < 8; kc++) {
        __syncthreads();
        float4* ws4 = (float4*)ws;
        ws4[tid] = wt0;
        ws4[tid + 256] = wt1;
        __syncthreads();
        if (kc < 7) {                        // prefetch next chunk
            const float4* wg = (const float4*)(Wp + (kc + 1) * 16 * D);
            wt0 = wg[tid]; wt1 = wg[tid + 256];
        }
        double2 wreg[16];
        #pragma unroll
        for (int kk = 0; kk < 16; kk++)
            wreg[kk] = *(const double2*)&ws[kk * D + col];
        #pragma unroll
        for (int i = 0; i < 8; i++) {
            const float4* xr = (const float4*)&xs[(row + i) * D + kc * 16];
            float4 xa = xr[0], xb = xr[1], xc = xr[2], xd = xr[3];
            #pragma unroll
            for (int kk = 0; kk < 16; kk++) {
                double xv2 = splat2(fcomp16(xa, xb, xc, xd, kk));
                fma2(acc[i][0], xv2, wreg[kk].x);
                fma2(acc[i][1], xv2, wreg[kk].y);
            }
        }
    }
    float alpha = 1.f / (1.f + __expf(-skip[t]));
    float onema = 1.f - alpha;
    float4 bb = *(const float4*)&ba[t * D + col];
    #pragma unroll
    for (int i = 0; i < 8; i++) {
        size_t off = (size_t)(node0 + row + i) * D + col;
        float4 xv = *(const float4*)&x[off];
        float2 p0 = unpack2(acc[i][0]);
        float2 p1 = unpack2(acc[i][1]);
        float4 rr;
        rr.x = (p0.x + bb.x) * alpha + xv.x * onema;
        rr.y = (p0.y + bb.y) * alpha + xv.y * onema;
        rr.z = (p1.x + bb.z) * alpha + xv.z * onema;
        rr.w = (p1.y + bb.w) * alpha + xv.w * onema;
        *(float4*)&out[off] = rr;
    }
}

// ---------------- launch ------------------------------------------------------
extern "C" void kernel_launch(void* const* d_in, const int* in_sizes, int n_in,
                              void* d_out, int out_size)
{
    const float* x       = (const float*)d_in[0];
    const int*   src     = (const int*)  d_in[1];
    const int*   dst     = (const int*)  d_in[2];
    const float* Wk      = (const float*)d_in[3];
    const float* bk      = (const float*)d_in[4];
    const float* Wq      = (const float*)d_in[5];
    const float* bq      = (const float*)d_in[6];
    const float* Wv      = (const float*)d_in[7];
    const float* bv      = (const float*)d_in[8];
    const float* Wa      = (const float*)d_in[9];
    const float* ba      = (const float*)d_in[10];
    const float* rel_att = (const float*)d_in[11];
    const float* rel_msg = (const float*)d_in[12];
    const float* rel_pri = (const float*)d_in[13];
    const float* nta     = (const float*)d_in[14];
    const float* nta1    = (const float*)d_in[15];
    const float* skip    = (const float*)d_in[16];
    const float* weight  = (const float*)d_in[17];
    const float* attn_w  = (const float*)d_in[18];
    float* out = (float*)d_out;

    proj3_kernel<<<N_NODES / 64, 256>>>(x, Wk, bk, Wq, bq, Wv, bv);
    edge_score_kernel<<<dim3(EBLK5, NUM_R), 512>>>(src, dst, rel_att, rel_pri, nta, nta1, weight, attn_w);
    deninv_kernel<<<((NUM_R * NT_NODES * NH) / 4 + 255) / 256, 256>>>();
    edge_accum_kernel<<<dim3(EBLK5, NUM_R), 512>>>(src, dst, rel_msg);
    final_kernel<<<N_NODES / 64, 256>>>(x, Wa, ba, skip, out);
}